// round 4
// baseline (speedup 1.0000x reference)
#include <cuda_runtime.h>
#include <math.h>

#define N_ENT 200000
#define N_USR 100000
#define DIM   64
#define E_N   1500000
#define NI_N  1000000
#define N_RELM1 10
#define HALF_D 32   // float2 lanes per row
#define KC   16     // cached edges per warp
#define WPB  8      // warps per block
#define EBLK ((N_ENT + WPB - 1) / WPB)   // 25000
#define UBLK ((N_USR + WPB - 1) / WPB)   // 12500

// ---------------- device scratch (no allocation allowed) ----------------
__device__ int   g_remap[16];
__device__ int   g_cnt_ent[N_ENT];
__device__ int   g_off_ent[N_ENT + 1];
__device__ int   g_cnt_usr[N_USR];
__device__ int   g_off_usr[N_USR + 1];
__device__ int   g_packed[E_N];      // tail | (virt<<18)
__device__ int   g_items[NI_N];
__device__ int   g_part_ent[512];
__device__ int   g_part_usr[512];
__device__ float g_entB[N_ENT * DIM];
__device__ float g_usrB[N_USR * DIM];

// ---------------- helpers ----------------
__device__ __forceinline__ float wsum(float v) {
    #pragma unroll
    for (int o = 16; o > 0; o >>= 1) v += __shfl_xor_sync(0xffffffffu, v, o);
    return v;
}

// squash(acc/den) + base   (squash = (sq/(sq+1)) * u / max(||u||, eps))
__device__ __forceinline__ float2 squash_add(float2 acc, float den, float2 base) {
    float x = acc.x / den, y = acc.y / den;
    float sq = wsum(x * x + y * y);
    float nrm = sqrtf(sq);
    float s = (sq / (sq + 1.0f)) / fmaxf(nrm, 1e-12f);
    return make_float2(x * s + base.x, y * s + base.y);
}

// ---------------- preprocessing kernels ----------------
__global__ void remap_kernel(const float* __restrict__ relw,
                             const float* __restrict__ lat) {
    int r = threadIdx.x;
    if (r >= N_RELM1) return;
    float best = -1e30f; int bi = 0;
    for (int v = 0; v < 3; v++) {
        float s = 0.f;
        for (int k = 0; k < DIM; k++) s += relw[r * DIM + k] * lat[v * DIM + k];
        if (s > best) { best = s; bi = v; }
    }
    g_remap[r] = bi;
}

__global__ void zero_k(int* __restrict__ p, int n) {
    for (int i = blockIdx.x * blockDim.x + threadIdx.x; i < n; i += gridDim.x * blockDim.x)
        p[i] = 0;
}

__global__ void hist_k(const int* __restrict__ keys, int* __restrict__ cnt, int n) {
    for (int i = blockIdx.x * blockDim.x + threadIdx.x; i < n; i += gridDim.x * blockDim.x)
        atomicAdd(&cnt[keys[i]], 1);
}

__global__ void block_sums_k(const int* __restrict__ in, int* __restrict__ part, int n) {
    __shared__ int sh[1024];
    int g = blockIdx.x * 1024 + threadIdx.x;
    sh[threadIdx.x] = (g < n) ? in[g] : 0;
    __syncthreads();
    for (int d = 512; d > 0; d >>= 1) {
        if (threadIdx.x < d) sh[threadIdx.x] += sh[threadIdx.x + d];
        __syncthreads();
    }
    if (threadIdx.x == 0) part[blockIdx.x] = sh[0];
}

__global__ void scan_partials_k(int* __restrict__ p, int n) {
    __shared__ int sh[256];
    int v = (threadIdx.x < n) ? p[threadIdx.x] : 0;
    sh[threadIdx.x] = v;
    __syncthreads();
    for (int d = 1; d < 256; d <<= 1) {
        int t = (threadIdx.x >= d) ? sh[threadIdx.x - d] : 0;
        __syncthreads();
        sh[threadIdx.x] += t;
        __syncthreads();
    }
    if (threadIdx.x < n) p[threadIdx.x] = sh[threadIdx.x] - v;  // exclusive
}

__global__ void scan_write_k(const int* __restrict__ in, const int* __restrict__ part,
                             int* __restrict__ off, int n) {
    __shared__ int sh[1024];
    int g = blockIdx.x * 1024 + threadIdx.x;
    int v = (g < n) ? in[g] : 0;
    sh[threadIdx.x] = v;
    __syncthreads();
    for (int d = 1; d < 1024; d <<= 1) {
        int t = (threadIdx.x >= d) ? sh[threadIdx.x - d] : 0;
        __syncthreads();
        sh[threadIdx.x] += t;
        __syncthreads();
    }
    int base = part[blockIdx.x];
    if (g < n) off[g] = base + sh[threadIdx.x] - v;   // exclusive scan
    if (g == n - 1) off[n] = base + sh[threadIdx.x];  // total
}

__global__ void scatter_ent_k(const int* __restrict__ head, const int* __restrict__ tail,
                              const int* __restrict__ et, const int* __restrict__ off,
                              int* __restrict__ cur, int* __restrict__ packed, int n) {
    for (int i = blockIdx.x * blockDim.x + threadIdx.x; i < n; i += gridDim.x * blockDim.x) {
        int h = head[i];
        int pos = off[h] + atomicAdd(&cur[h], 1);
        int v = g_remap[et[i] - 1];
        packed[pos] = tail[i] | (v << 18);
    }
}

__global__ void scatter_usr_k(const int* __restrict__ uid, const int* __restrict__ iid,
                              const int* __restrict__ off, int* __restrict__ cur,
                              int* __restrict__ items, int n) {
    for (int i = blockIdx.x * blockDim.x + threadIdx.x; i < n; i += gridDim.x * blockDim.x) {
        int u = uid[i];
        int pos = off[u] + atomicAdd(&cur[u], 1);
        items[pos] = iid[i];
    }
}

// ---------------- fused hop kernel: entity blocks + user blocks ----------------
__global__ void __launch_bounds__(256)
fused_hop_k(const float2* __restrict__ ent_in, const float2* __restrict__ usr_in,
            const float* __restrict__ aggw, int hop, int init,
            const int* __restrict__ off_e, const int* __restrict__ packed,
            const int* __restrict__ off_u, const int* __restrict__ items,
            float2* __restrict__ ent_store, float2* __restrict__ usr_store,
            float2* __restrict__ res_ent, float2* __restrict__ res_usr)
{
    __shared__ float2 s_rows[WPB][KC][HALF_D];
    __shared__ float  s_d[WPB][KC];

    const int wid  = threadIdx.x >> 5;
    const int lane = threadIdx.x & 31;
    float2* __restrict__ srow = &s_rows[wid][0][0];
    float*  __restrict__ sd   = s_d[wid];

    if (blockIdx.x < EBLK) {
        // ======================= ENTITY =======================
        int w = blockIdx.x * WPB + wid;
        if (w >= N_ENT) return;

        float2 en = ent_in[w * HALF_D + lane];
        int s = off_e[w], e = off_e[w + 1];
        int deg = e - s;
        int nc = min(deg, KC);
        int pkreg = (lane < nc) ? packed[s + lane] : 0;

        // softmax(agg_w[hop])
        float a0 = aggw[hop * 3 + 0], a1 = aggw[hop * 3 + 1], a2 = aggw[hop * 3 + 2];
        float mx = fmaxf(a0, fmaxf(a1, a2));
        float e0 = expf(a0 - mx), e1 = expf(a1 - mx), e2 = expf(a2 - mx);
        float inv = 1.0f / (e0 + e1 + e2);
        float w0 = e0 * inv, w1 = e1 * inv, w2 = e2 * inv;

        // ---- fill cache + pass0: plain per-virt sums ----
        float2 A0 = {0, 0}, A1 = {0, 0}, A2 = {0, 0};
        int c0 = 0, c1 = 0, c2 = 0;
        for (int j = 0; j < nc; j++) {
            int p = __shfl_sync(0xffffffffu, pkreg, j);
            int t = p & 0x3FFFF, v = p >> 18;
            float2 nt = ent_in[t * HALF_D + lane];
            srow[j * HALF_D + lane] = nt;
            if (v == 0)      { A0.x += nt.x; A0.y += nt.y; c0++; }
            else if (v == 1) { A1.x += nt.x; A1.y += nt.y; c1++; }
            else             { A2.x += nt.x; A2.y += nt.y; c2++; }
        }
        for (int b = s + nc; b < e; b += 32) {           // rare tail (deg > KC)
            int m = min(32, e - b);
            int pk = (lane < m) ? packed[b + lane] : 0;
            for (int j = 0; j < m; j++) {
                int p = __shfl_sync(0xffffffffu, pk, j);
                int t = p & 0x3FFFF, v = p >> 18;
                float2 nt = ent_in[t * HALF_D + lane];
                if (v == 0)      { A0.x += nt.x; A0.y += nt.y; c0++; }
                else if (v == 1) { A1.x += nt.x; A1.y += nt.y; c1++; }
                else             { A2.x += nt.x; A2.y += nt.y; c2++; }
            }
        }
        float d0 = fmaxf((float)c0, 1.f), d1 = fmaxf((float)c1, 1.f), d2 = fmaxf((float)c2, 1.f);
        float2 u10 = squash_add(A0, d0, en);
        float2 u11 = squash_add(A1, d1, en);
        float2 u12 = squash_add(A2, d2, en);

        // ---- pass1: sim-weighted (4-wide interleaved reductions, dots cached to sd) ----
        A0 = make_float2(0, 0); A1 = make_float2(0, 0); A2 = make_float2(0, 0);
        for (int j0 = 0; j0 < nc; j0 += 4) {
            float p[4]; int vv[4];
            #pragma unroll
            for (int q = 0; q < 4; q++) {
                int j = j0 + q;
                if (j < nc) {
                    int pm = __shfl_sync(0xffffffffu, pkreg, j);
                    int v = pm >> 18; vv[q] = v;
                    float2 nt = srow[j * HALF_D + lane];
                    float2 uv = (v == 0) ? u10 : ((v == 1) ? u11 : u12);
                    p[q] = uv.x * nt.x + uv.y * nt.y;
                } else { p[q] = 0.f; vv[q] = -1; }
            }
            #pragma unroll
            for (int o = 16; o > 0; o >>= 1) {
                #pragma unroll
                for (int q = 0; q < 4; q++) p[q] += __shfl_xor_sync(0xffffffffu, p[q], o);
            }
            #pragma unroll
            for (int q = 0; q < 4; q++) {
                int j = j0 + q;
                if (j < nc) {
                    float2 nt = srow[j * HALF_D + lane];
                    float d = p[q];
                    if (lane == 0) sd[j] = d;
                    int v = vv[q];
                    if (v == 0)      { A0.x += d * nt.x; A0.y += d * nt.y; }
                    else if (v == 1) { A1.x += d * nt.x; A1.y += d * nt.y; }
                    else             { A2.x += d * nt.x; A2.y += d * nt.y; }
                }
            }
        }
        for (int b = s + nc; b < e; b += 32) {           // rare tail
            int m = min(32, e - b);
            int pk = (lane < m) ? packed[b + lane] : 0;
            for (int j = 0; j < m; j++) {
                int p = __shfl_sync(0xffffffffu, pk, j);
                int t = p & 0x3FFFF, v = p >> 18;
                float2 nt = ent_in[t * HALF_D + lane];
                float2 uv = (v == 0) ? u10 : ((v == 1) ? u11 : u12);
                float d = wsum(uv.x * nt.x + uv.y * nt.y);
                if (v == 0)      { A0.x += d * nt.x; A0.y += d * nt.y; }
                else if (v == 1) { A1.x += d * nt.x; A1.y += d * nt.y; }
                else             { A2.x += d * nt.x; A2.y += d * nt.y; }
            }
        }
        float2 u20 = squash_add(A0, d0, en);
        float2 u21 = squash_add(A1, d1, en);
        float2 u22 = squash_add(A2, d2, en);

        __syncwarp();   // sd visibility across lanes

        // ---- pass2: cumulative sim (sd[j]^2 * d2), 4-wide interleaved ----
        A0 = make_float2(0, 0); A1 = make_float2(0, 0); A2 = make_float2(0, 0);
        for (int j0 = 0; j0 < nc; j0 += 4) {
            float p[4]; int vv[4];
            #pragma unroll
            for (int q = 0; q < 4; q++) {
                int j = j0 + q;
                if (j < nc) {
                    int pm = __shfl_sync(0xffffffffu, pkreg, j);
                    int v = pm >> 18; vv[q] = v;
                    float2 nt = srow[j * HALF_D + lane];
                    float2 uB = (v == 0) ? u20 : ((v == 1) ? u21 : u22);
                    p[q] = uB.x * nt.x + uB.y * nt.y;
                } else { p[q] = 0.f; vv[q] = -1; }
            }
            #pragma unroll
            for (int o = 16; o > 0; o >>= 1) {
                #pragma unroll
                for (int q = 0; q < 4; q++) p[q] += __shfl_xor_sync(0xffffffffu, p[q], o);
            }
            #pragma unroll
            for (int q = 0; q < 4; q++) {
                int j = j0 + q;
                if (j < nc) {
                    float2 nt = srow[j * HALF_D + lane];
                    float pa = sd[j];
                    float sc = pa * pa * p[q];
                    int v = vv[q];
                    if (v == 0)      { A0.x += sc * nt.x; A0.y += sc * nt.y; }
                    else if (v == 1) { A1.x += sc * nt.x; A1.y += sc * nt.y; }
                    else             { A2.x += sc * nt.x; A2.y += sc * nt.y; }
                }
            }
        }
        for (int b = s + nc; b < e; b += 32) {           // rare tail: recompute both dots
            int m = min(32, e - b);
            int pk = (lane < m) ? packed[b + lane] : 0;
            for (int j = 0; j < m; j++) {
                int p = __shfl_sync(0xffffffffu, pk, j);
                int t = p & 0x3FFFF, v = p >> 18;
                float2 nt = ent_in[t * HALF_D + lane];
                float2 uA = (v == 0) ? u10 : ((v == 1) ? u11 : u12);
                float2 uB = (v == 0) ? u20 : ((v == 1) ? u21 : u22);
                float pa = uA.x * nt.x + uA.y * nt.y;
                float pb = uB.x * nt.x + uB.y * nt.y;
                #pragma unroll
                for (int o = 16; o > 0; o >>= 1) {
                    pa += __shfl_xor_sync(0xffffffffu, pa, o);
                    pb += __shfl_xor_sync(0xffffffffu, pb, o);
                }
                float sc = pa * pa * pb;
                if (v == 0)      { A0.x += sc * nt.x; A0.y += sc * nt.y; }
                else if (v == 1) { A1.x += sc * nt.x; A1.y += sc * nt.y; }
                else             { A2.x += sc * nt.x; A2.y += sc * nt.y; }
            }
        }
        float2 u30 = make_float2(A0.x / d0 + en.x, A0.y / d0 + en.y);
        float2 u31 = make_float2(A1.x / d1 + en.x, A1.y / d1 + en.y);
        float2 u32 = make_float2(A2.x / d2 + en.x, A2.y / d2 + en.y);

        float2 ag = make_float2(w0 * u30.x + w1 * u31.x + w2 * u32.x,
                                w0 * u30.y + w1 * u31.y + w2 * u32.y);
        float sq = wsum(ag.x * ag.x + ag.y * ag.y);
        float in2 = 1.0f / fmaxf(sqrtf(sq), 1e-12f);
        float2 o = make_float2(ag.x * in2, ag.y * in2);
        if (ent_store) ent_store[w * HALF_D + lane] = o;
        float2 r;
        if (init) { r.x = en.x + o.x; r.y = en.y + o.y; }
        else { r = res_ent[w * HALF_D + lane]; r.x += o.x; r.y += o.y; }
        res_ent[w * HALF_D + lane] = r;

    } else {
        // ======================= USER =======================
        int w = (blockIdx.x - EBLK) * WPB + wid;
        if (w >= N_USR) return;

        float2 un = usr_in[w * HALF_D + lane];
        int s = off_u[w], e = off_u[w + 1];
        int deg = e - s;
        float den = fmaxf((float)deg, 1.f);
        int nc = min(deg, KC);
        int itreg = (lane < nc) ? items[s + lane] : 0;

        // ---- fill cache + it0 ----
        float2 A = {0, 0};
        for (int j = 0; j < nc; j++) {
            int t = __shfl_sync(0xffffffffu, itreg, j);
            float2 nt = ent_in[t * HALF_D + lane];
            srow[j * HALF_D + lane] = nt;
            A.x += nt.x; A.y += nt.y;
        }
        for (int b = s + nc; b < e; b += 32) {
            int m = min(32, e - b);
            int it = (lane < m) ? items[b + lane] : 0;
            for (int j = 0; j < m; j++) {
                int t = __shfl_sync(0xffffffffu, it, j);
                float2 nt = ent_in[t * HALF_D + lane];
                A.x += nt.x; A.y += nt.y;
            }
        }
        float2 u1 = squash_add(A, den, un);

        // ---- it1: sim with u1 (4-wide) ----
        A = make_float2(0, 0);
        for (int j0 = 0; j0 < nc; j0 += 4) {
            float p[4];
            #pragma unroll
            for (int q = 0; q < 4; q++) {
                int j = j0 + q;
                if (j < nc) {
                    float2 nt = srow[j * HALF_D + lane];
                    p[q] = u1.x * nt.x + u1.y * nt.y;
                } else p[q] = 0.f;
            }
            #pragma unroll
            for (int o = 16; o > 0; o >>= 1) {
                #pragma unroll
                for (int q = 0; q < 4; q++) p[q] += __shfl_xor_sync(0xffffffffu, p[q], o);
            }
            #pragma unroll
            for (int q = 0; q < 4; q++) {
                int j = j0 + q;
                if (j < nc) {
                    float2 nt = srow[j * HALF_D + lane];
                    A.x += p[q] * nt.x; A.y += p[q] * nt.y;
                }
            }
        }
        for (int b = s + nc; b < e; b += 32) {
            int m = min(32, e - b);
            int it = (lane < m) ? items[b + lane] : 0;
            for (int j = 0; j < m; j++) {
                int t = __shfl_sync(0xffffffffu, it, j);
                float2 nt = ent_in[t * HALF_D + lane];
                float d = wsum(u1.x * nt.x + u1.y * nt.y);
                A.x += d * nt.x; A.y += d * nt.y;
            }
        }
        float2 u2 = squash_add(A, den, un);

        // ---- it2: sim with u2 (4-wide), no squash ----
        A = make_float2(0, 0);
        for (int j0 = 0; j0 < nc; j0 += 4) {
            float p[4];
            #pragma unroll
            for (int q = 0; q < 4; q++) {
                int j = j0 + q;
                if (j < nc) {
                    float2 nt = srow[j * HALF_D + lane];
                    p[q] = u2.x * nt.x + u2.y * nt.y;
                } else p[q] = 0.f;
            }
            #pragma unroll
            for (int o = 16; o > 0; o >>= 1) {
                #pragma unroll
                for (int q = 0; q < 4; q++) p[q] += __shfl_xor_sync(0xffffffffu, p[q], o);
            }
            #pragma unroll
            for (int q = 0; q < 4; q++) {
                int j = j0 + q;
                if (j < nc) {
                    float2 nt = srow[j * HALF_D + lane];
                    A.x += p[q] * nt.x; A.y += p[q] * nt.y;
                }
            }
        }
        for (int b = s + nc; b < e; b += 32) {
            int m = min(32, e - b);
            int it = (lane < m) ? items[b + lane] : 0;
            for (int j = 0; j < m; j++) {
                int t = __shfl_sync(0xffffffffu, it, j);
                float2 nt = ent_in[t * HALF_D + lane];
                float d = wsum(u2.x * nt.x + u2.y * nt.y);
                A.x += d * nt.x; A.y += d * nt.y;
            }
        }
        float2 u3 = make_float2(A.x / den + un.x, A.y / den + un.y);

        float sq = wsum(u3.x * u3.x + u3.y * u3.y);
        float in2 = 1.0f / fmaxf(sqrtf(sq), 1e-12f);
        float2 o = make_float2(u3.x * in2, u3.y * in2);
        if (usr_store) usr_store[w * HALF_D + lane] = o;
        float2 r;
        if (init) { r.x = un.x + o.x; r.y = un.y + o.y; }
        else { r = res_usr[w * HALF_D + lane]; r.x += o.x; r.y += o.y; }
        res_usr[w * HALF_D + lane] = r;
    }
}

// ---------------- launch ----------------
extern "C" void kernel_launch(void* const* d_in, const int* in_sizes, int n_in,
                              void* d_out, int out_size) {
    const float* entity_emb = (const float*)d_in[0];
    const float* user_emb   = (const float*)d_in[1];
    const float* latent     = (const float*)d_in[2];
    const float* relw       = (const float*)d_in[3];
    const float* aggw       = (const float*)d_in[4];
    const int*   eidx       = (const int*)d_in[5];   // [2,E]: head row then tail row
    const int*   etype      = (const int*)d_in[6];
    const int*   uidx       = (const int*)d_in[7];
    const int*   iidx       = (const int*)d_in[8];
    float* out = (float*)d_out;

    int *p_cnt_ent, *p_off_ent, *p_cnt_usr, *p_off_usr, *p_packed, *p_items, *p_pe, *p_pu;
    float *p_entB, *p_usrB;
    cudaGetSymbolAddress((void**)&p_cnt_ent, g_cnt_ent);
    cudaGetSymbolAddress((void**)&p_off_ent, g_off_ent);
    cudaGetSymbolAddress((void**)&p_cnt_usr, g_cnt_usr);
    cudaGetSymbolAddress((void**)&p_off_usr, g_off_usr);
    cudaGetSymbolAddress((void**)&p_packed,  g_packed);
    cudaGetSymbolAddress((void**)&p_items,   g_items);
    cudaGetSymbolAddress((void**)&p_pe,      g_part_ent);
    cudaGetSymbolAddress((void**)&p_pu,      g_part_usr);
    cudaGetSymbolAddress((void**)&p_entB,    g_entB);
    cudaGetSymbolAddress((void**)&p_usrB,    g_usrB);

    remap_kernel<<<1, 32>>>(relw, latent);

    zero_k<<<(N_ENT + 1023) / 1024, 1024>>>(p_cnt_ent, N_ENT);
    zero_k<<<(N_USR + 1023) / 1024, 1024>>>(p_cnt_usr, N_USR);

    hist_k<<<1024, 256>>>(eidx, p_cnt_ent, E_N);       // heads
    hist_k<<<1024, 256>>>(uidx, p_cnt_usr, NI_N);

    const int NB_E = (N_ENT + 1023) / 1024;  // 196
    const int NB_U = (N_USR + 1023) / 1024;  // 98
    block_sums_k<<<NB_E, 1024>>>(p_cnt_ent, p_pe, N_ENT);
    scan_partials_k<<<1, 256>>>(p_pe, NB_E);
    scan_write_k<<<NB_E, 1024>>>(p_cnt_ent, p_pe, p_off_ent, N_ENT);
    block_sums_k<<<NB_U, 1024>>>(p_cnt_usr, p_pu, N_USR);
    scan_partials_k<<<1, 256>>>(p_pu, NB_U);
    scan_write_k<<<NB_U, 1024>>>(p_cnt_usr, p_pu, p_off_usr, N_USR);

    zero_k<<<(N_ENT + 1023) / 1024, 1024>>>(p_cnt_ent, N_ENT);
    zero_k<<<(N_USR + 1023) / 1024, 1024>>>(p_cnt_usr, N_USR);

    scatter_ent_k<<<2048, 256>>>(eidx, eidx + E_N, etype, p_off_ent, p_cnt_ent, p_packed, E_N);
    scatter_usr_k<<<2048, 256>>>(uidx, iidx, p_off_usr, p_cnt_usr, p_items, NI_N);

    float2* res_e = (float2*)out;
    float2* res_u = (float2*)(out + (size_t)N_ENT * DIM);

    // hop 0: inputs = base embeddings; init residual in-kernel; store normalized hop output
    fused_hop_k<<<EBLK + UBLK, 256>>>(
        (const float2*)entity_emb, (const float2*)user_emb, aggw, 0, 1,
        p_off_ent, p_packed, p_off_usr, p_items,
        (float2*)p_entB, (float2*)p_usrB, res_e, res_u);

    // hop 1: inputs = hop-0 normalized outputs; accumulate residual only
    fused_hop_k<<<EBLK + UBLK, 256>>>(
        (const float2*)p_entB, (const float2*)p_usrB, aggw, 1, 0,
        p_off_ent, p_packed, p_off_usr, p_items,
        nullptr, nullptr, res_e, res_u);
}